// round 5
// baseline (speedup 1.0000x reference)
#include <cuda_runtime.h>
#include <cuda_bf16.h>
#include <math.h>
#include <stdint.h>

#define DIMV 1024
#define NHEADS 16
#define DK 64
#define RFF 128
#define FEAT 256
#define BATCH 2
#define SEQ 8192
#define MROWS 16384
#define BH 32
#define NPAD 96
#define INV_SQRT_R 0.08838834764831845f

typedef __nv_bfloat16 bf16;
typedef __nv_bfloat162 bf162;

// ---------------- scratch (device globals) ----------------
__device__ bf16 g_xh[MROWS*DIMV], g_xl[MROWS*DIMV];
__device__ bf16 g_wh[4*DIMV*DIMV], g_wl[4*DIMV*DIMV];
__device__ bf16 g_qh[MROWS*DIMV], g_ql[MROWS*DIMV];
__device__ bf16 g_kh[MROWS*DIMV], g_kl[MROWS*DIMV];
__device__ bf16 g_vth[BH*NPAD*SEQ], g_vtl[BH*NPAD*SEQ];
__device__ bf16 g_wrth[NHEADS*RFF*DK], g_wrtl[NHEADS*RFF*DK];
__device__ bf16 g_qfh[(size_t)BH*SEQ*FEAT], g_qfl[(size_t)BH*SEQ*FEAT];
__device__ bf16 g_kfh[(size_t)BH*FEAT*SEQ], g_kfl[(size_t)BH*FEAT*SEQ];
__device__ float g_kvp[8*BH*FEAT*NPAD];
__device__ bf16 g_dth[BH*NPAD*FEAT], g_dtl[BH*NPAD*FEAT];
__device__ bf16 g_ah[MROWS*DIMV], g_al[MROWS*DIMV];

// ---------------- helpers ----------------
__device__ __forceinline__ uint32_t smem_u32(const void* p) {
    uint32_t a;
    asm("{ .reg .u64 t; cvta.to.shared.u64 t, %1; cvt.u32.u64 %0, t; }" : "=r"(a) : "l"(p));
    return a;
}
__device__ __forceinline__ void cpa16(uint32_t s, const void* g) {
    asm volatile("cp.async.cg.shared.global [%0], [%1], 16;" :: "r"(s), "l"(g));
}
__device__ __forceinline__ void cpa_commit() { asm volatile("cp.async.commit_group;"); }
__device__ __forceinline__ void ldmx4(uint32_t addr, uint32_t& r0, uint32_t& r1, uint32_t& r2, uint32_t& r3) {
    asm volatile("ldmatrix.sync.aligned.m8n8.x4.shared.b16 {%0,%1,%2,%3}, [%4];"
                 : "=r"(r0), "=r"(r1), "=r"(r2), "=r"(r3) : "r"(addr));
}
__device__ __forceinline__ void mma16816(float* d, const uint32_t* a, const uint32_t* b) {
    asm volatile(
        "mma.sync.aligned.m16n8k16.row.col.f32.bf16.bf16.f32 "
        "{%0,%1,%2,%3}, {%4,%5,%6,%7}, {%8,%9}, {%0,%1,%2,%3};"
        : "+f"(d[0]), "+f"(d[1]), "+f"(d[2]), "+f"(d[3])
        : "r"(a[0]), "r"(a[1]), "r"(a[2]), "r"(a[3]), "r"(b[0]), "r"(b[1]));
}
__device__ __forceinline__ void bsplit(float v, bf16& h, bf16& l) {
    h = __float2bfloat16(v);
    l = __float2bfloat16(v - __bfloat162float(h));
}
__device__ __forceinline__ bf162 mk2(bf16 a, bf16 b) { bf162 t; t.x = a; t.y = b; return t; }

// ---------------- fp32 -> (hi, lo) bf16 split ----------------
__global__ __launch_bounds__(256) void split_bf16(
    const float* __restrict__ in, bf16* __restrict__ hi, bf16* __restrict__ lo, int n4)
{
    int i = blockIdx.x * 256 + threadIdx.x;
    if (i >= n4) return;
    float4 v = ((const float4*)in)[i];
    bf16 h0, l0, h1, l1, h2, l2, h3, l3;
    bsplit(v.x, h0, l0); bsplit(v.y, h1, l1); bsplit(v.z, h2, l2); bsplit(v.w, h3, l3);
    ((bf162*)hi)[2*i]   = mk2(h0, h1);
    ((bf162*)hi)[2*i+1] = mk2(h2, h3);
    ((bf162*)lo)[2*i]   = mk2(l0, l1);
    ((bf162*)lo)[2*i+1] = mk2(l2, l3);
}

// ---------------- WrT prep ----------------
__global__ __launch_bounds__(256) void prep_wrt(const float* __restrict__ Wr)
{
    int h = blockIdx.x;
    for (int e = threadIdx.x; e < RFF * DK; e += 256) {
        int r = e >> 6, j = e & 63;
        float v = Wr[(size_t)h * DK * RFF + j * RFF + r];
        bf16 hi, lo; bsplit(v, hi, lo);
        g_wrth[h * RFF * DK + e] = hi;
        g_wrtl[h * RFF * DK + e] = lo;
    }
}

// ---------------- vT padding rows ----------------
__global__ __launch_bounds__(256) void fill_vt()
{
    int bx = blockIdx.x;
    int bh = bx >> 5, dr = 64 + (bx & 31);
    bf16 v = __float2bfloat16(dr == 64 ? 1.f : 0.f);
    bf16 z = __float2bfloat16(0.f);
    bf162 vv = mk2(v, v), zz = mk2(z, z);
    size_t base = ((size_t)bh * NPAD + dr) * SEQ;
    for (int i = threadIdx.x; i < SEQ / 2; i += 256) {
        *(bf162*)&g_vth[base + 2 * i] = vv;
        *(bf162*)&g_vtl[base + 2 * i] = zz;
    }
}

// ---------------- big bf16x3 GEMM, 3-stage pipeline, hoisted fragments ----------------
// MODE 0: fp32 + bias (final).  MODE 3: merged QKV (N=3072): cols<1024 -> q,
// <2048 -> k, else v transposed per head.
#define GSTAGE 32768
#define GEMM_SMEM (3 * GSTAGE)

template<int MODE>
__global__ __launch_bounds__(256, 1) void gemm3(
    const bf16* __restrict__ Ah, const bf16* __restrict__ Al,
    const bf16* __restrict__ Bh, const bf16* __restrict__ Bl,
    const float* __restrict__ bias, float* __restrict__ C)
{
    extern __shared__ __align__(128) char sm[];
    const int tid = threadIdx.x, wid = tid >> 5, lid = tid & 31;
    const int m0 = blockIdx.y * 128, n0 = blockIdx.x * 128;
    const int wm = (wid & 1) * 64;
    const int wn = (wid >> 1) * 32;
    const uint32_t smb = smem_u32(sm);

    float acc[4][4][4];
    #pragma unroll
    for (int i = 0; i < 4; i++)
        #pragma unroll
        for (int j = 0; j < 4; j++)
            #pragma unroll
            for (int e = 0; e < 4; e++) acc[i][j][e] = 0.f;

    auto load_stage = [&](int ci, int s) {
        const int k0 = ci * 32;
        const uint32_t sb = smb + s * GSTAGE;
        #pragma unroll
        for (int it = 0; it < 2; it++) {
            int t = tid + it * 256;
            int row = t >> 2, q = t & 3;
            uint32_t soff = row * 64 + ((q ^ ((row >> 1) & 3)) << 4);
            size_t ga = (size_t)(m0 + row) * DIMV + k0 + q * 8;
            size_t gb = (size_t)(n0 + row) * DIMV + k0 + q * 8;
            cpa16(sb + soff,         Ah + ga);
            cpa16(sb + 8192  + soff, Al + ga);
            cpa16(sb + 16384 + soff, Bh + gb);
            cpa16(sb + 24576 + soff, Bl + gb);
        }
        cpa_commit();
    };

    load_stage(0, 0);
    load_stage(1, 1);

    int s = 0;
    #pragma unroll 1
    for (int ci = 0; ci < 32; ci++) {
        if (ci < 31) asm volatile("cp.async.wait_group 1;");
        else         asm volatile("cp.async.wait_group 0;");
        __syncthreads();
        if (ci + 2 < 32) {
            int s2 = s + 2; if (s2 >= 3) s2 -= 3;
            load_stage(ci + 2, s2);
        }

        const uint32_t sb = smb + s * GSTAGE;
        // hoist ALL fragment loads for both k-steps before any MMA
        uint32_t aH[2][4][4], aL[2][4][4], bH[2][4][2], bL[2][4][2];
        #pragma unroll
        for (int ks = 0; ks < 2; ks++) {
            #pragma unroll
            for (int mi = 0; mi < 4; mi++) {
                int row = wm + mi * 16 + (lid & 7) + ((lid >> 3) & 1) * 8;
                int q = ks * 2 + (lid >> 4);
                uint32_t off = row * 64 + ((q ^ ((row >> 1) & 3)) << 4);
                ldmx4(sb + off,        aH[ks][mi][0], aH[ks][mi][1], aH[ks][mi][2], aH[ks][mi][3]);
                ldmx4(sb + 8192 + off, aL[ks][mi][0], aL[ks][mi][1], aL[ks][mi][2], aL[ks][mi][3]);
            }
            #pragma unroll
            for (int np = 0; np < 2; np++) {
                int row = wn + np * 16 + (lid >> 4) * 8 + (lid & 7);
                int q = ks * 2 + ((lid >> 3) & 1);
                uint32_t off = row * 64 + ((q ^ ((row >> 1) & 3)) << 4);
                ldmx4(sb + 16384 + off, bH[ks][2*np][0], bH[ks][2*np][1], bH[ks][2*np+1][0], bH[ks][2*np+1][1]);
                ldmx4(sb + 24576 + off, bL[ks][2*np][0], bL[ks][2*np][1], bL[ks][2*np+1][0], bL[ks][2*np+1][1]);
            }
        }
        #pragma unroll
        for (int ks = 0; ks < 2; ks++) {
            #pragma unroll
            for (int mi = 0; mi < 4; mi++)
                #pragma unroll
                for (int ni = 0; ni < 4; ni++)
                    mma16816(acc[mi][ni], aH[ks][mi], bH[ks][ni]);
            #pragma unroll
            for (int mi = 0; mi < 4; mi++)
                #pragma unroll
                for (int ni = 0; ni < 4; ni++)
                    mma16816(acc[mi][ni], aH[ks][mi], bL[ks][ni]);
            #pragma unroll
            for (int mi = 0; mi < 4; mi++)
                #pragma unroll
                for (int ni = 0; ni < 4; ni++)
                    mma16816(acc[mi][ni], aL[ks][mi], bH[ks][ni]);
        }
        __syncthreads();
        s++; if (s >= 3) s -= 3;
    }

    const int g = lid >> 2, c2 = (lid & 3) * 2;
    #pragma unroll
    for (int mi = 0; mi < 4; mi++) {
        #pragma unroll
        for (int ni = 0; ni < 4; ni++) {
            int row = m0 + wm + mi * 16 + g;
            int col = n0 + wn + ni * 8 + c2;
            if (MODE == 0) {
                float b0 = bias ? bias[col] : 0.f;
                float b1 = bias ? bias[col + 1] : 0.f;
                float2 o0 = { acc[mi][ni][0] + b0, acc[mi][ni][1] + b1 };
                float2 o1 = { acc[mi][ni][2] + b0, acc[mi][ni][3] + b1 };
                *(float2*)&C[(size_t)row * DIMV + col]       = o0;
                *(float2*)&C[(size_t)(row + 8) * DIMV + col] = o1;
            } else {
                if (col < 2048) {
                    bf16* Ch = (col < 1024) ? g_qh : g_kh;
                    bf16* Cl = (col < 1024) ? g_ql : g_kl;
                    int cc = col & 1023;
                    bf16 h0, l0, h1, l1;
                    bsplit(acc[mi][ni][0], h0, l0); bsplit(acc[mi][ni][1], h1, l1);
                    *(bf162*)&Ch[(size_t)row * DIMV + cc] = mk2(h0, h1);
                    *(bf162*)&Cl[(size_t)row * DIMV + cc] = mk2(l0, l1);
                    bsplit(acc[mi][ni][2], h0, l0); bsplit(acc[mi][ni][3], h1, l1);
                    *(bf162*)&Ch[(size_t)(row + 8) * DIMV + cc] = mk2(h0, h1);
                    *(bf162*)&Cl[(size_t)(row + 8) * DIMV + cc] = mk2(l0, l1);
                } else {
                    int cc = col - 2048;
                    int hh = cc >> 6, d0 = cc & 63;
                    int b = row >> 13, n = row & 8191;
                    size_t base = ((size_t)(b * NHEADS + hh) * NPAD) * SEQ;
                    bf16 h0, l0;
                    bsplit(acc[mi][ni][0], h0, l0);
                    g_vth[base + (size_t)d0 * SEQ + n] = h0;       g_vtl[base + (size_t)d0 * SEQ + n] = l0;
                    bsplit(acc[mi][ni][1], h0, l0);
                    g_vth[base + (size_t)(d0+1) * SEQ + n] = h0;   g_vtl[base + (size_t)(d0+1) * SEQ + n] = l0;
                    bsplit(acc[mi][ni][2], h0, l0);
                    g_vth[base + (size_t)d0 * SEQ + n + 8] = h0;   g_vtl[base + (size_t)d0 * SEQ + n + 8] = l0;
                    bsplit(acc[mi][ni][3], h0, l0);
                    g_vth[base + (size_t)(d0+1) * SEQ + n + 8] = h0; g_vtl[base + (size_t)(d0+1) * SEQ + n + 8] = l0;
                }
            }
        }
    }
}

// ---------------- proj + RFF features ----------------
#define PROJ_SMEM 65536

__global__ __launch_bounds__(256, 1) void proj_feat(const float* __restrict__ brp)
{
    extern __shared__ __align__(128) char sm[];
    const int tid = threadIdx.x, wid = tid >> 5, lid = tid & 31;
    const int m0 = blockIdx.x * 128;
    const int qk = blockIdx.y >> 4, h = blockIdx.y & 15;
    const int wm = (wid & 1) * 64, wn = (wid >> 1) * 32;
    const uint32_t smb = smem_u32(sm);

    const bf16* Ah = (qk ? g_kh : g_qh);
    const bf16* Al = (qk ? g_kl : g_ql);
    const bf16* Bh = g_wrth + h * RFF * DK;
    const bf16* Bl = g_wrtl + h * RFF * DK;

    #pragma unroll
    for (int it = 0; it < 4; it++) {
        int idx = tid + it * 256;
        int row = idx >> 3, q = idx & 7;
        uint32_t soff = row * 128 + ((q ^ (row & 7)) << 4);
        *(uint4*)(sm + soff)         = *(const uint4*)(Ah + (size_t)(m0 + row) * DIMV + h * DK + q * 8);
        *(uint4*)(sm + 16384 + soff) = *(const uint4*)(Al + (size_t)(m0 + row) * DIMV + h * DK + q * 8);
        *(uint4*)(sm + 32768 + soff) = *(const uint4*)(Bh + row * DK + q * 8);
        *(uint4*)(sm + 49152 + soff) = *(const uint4*)(Bl + row * DK + q * 8);
    }
    __syncthreads();

    float acc[4][4][4];
    #pragma unroll
    for (int i = 0; i < 4; i++)
        #pragma unroll
        for (int j = 0; j < 4; j++)
            #pragma unroll
            for (int e = 0; e < 4; e++) acc[i][j][e] = 0.f;

    #pragma unroll
    for (int ks = 0; ks < 4; ks++) {
        uint32_t aH[4][4], aL[4][4], bH[4][2], bL[4][2];
        #pragma unroll
        for (int mi = 0; mi < 4; mi++) {
            int row = wm + mi * 16 + (lid & 7) + ((lid >> 3) & 1) * 8;
            int q = ks * 2 + (lid >> 4);
            uint32_t off = row * 128 + ((q ^ (row & 7)) << 4);
            ldmx4(smb + off,         aH[mi][0], aH[mi][1], aH[mi][2], aH[mi][3]);
            ldmx4(smb + 16384 + off, aL[mi][0], aL[mi][1], aL[mi][2], aL[mi][3]);
        }
        #pragma unroll
        for (int np = 0; np < 2; np++) {
            int row = wn + np * 16 + (lid >> 4) * 8 + (lid & 7);
            int q = ks * 2 + ((lid >> 3) & 1);
            uint32_t off = row * 128 + ((q ^ (row & 7)) << 4);
            ldmx4(smb + 32768 + off, bH[2*np][0], bH[2*np][1], bH[2*np+1][0], bH[2*np+1][1]);
            ldmx4(smb + 49152 + off, bL[2*np][0], bL[2*np][1], bL[2*np+1][0], bL[2*np+1][1]);
        }
        #pragma unroll
        for (int mi = 0; mi < 4; mi++)
            #pragma unroll
            for (int ni = 0; ni < 4; ni++)
                mma16816(acc[mi][ni], aH[mi], bH[ni]);
        #pragma unroll
        for (int mi = 0; mi < 4; mi++)
            #pragma unroll
            for (int ni = 0; ni < 4; ni++)
                mma16816(acc[mi][ni], aH[mi], bL[ni]);
        #pragma unroll
        for (int mi = 0; mi < 4; mi++)
            #pragma unroll
            for (int ni = 0; ni < 4; ni++)
                mma16816(acc[mi][ni], aL[mi], bH[ni]);
    }

    const int g = lid >> 2, c2 = (lid & 3) * 2;
    #pragma unroll
    for (int mi = 0; mi < 4; mi++) {
        #pragma unroll
        for (int ni = 0; ni < 4; ni++) {
            int col = wn + ni * 8 + c2;
            float b0 = brp[h * RFF + col], b1 = brp[h * RFF + col + 1];
            #pragma unroll
            for (int half = 0; half < 2; half++) {
                int row = m0 + wm + mi * 16 + g + half * 8;
                int b = row >> 13, n = row & 8191;
                int bh = b * NHEADS + h;
                float p0 = acc[mi][ni][half * 2 + 0] + b0;
                float p1 = acc[mi][ni][half * 2 + 1] + b1;
                float s0, c0, s1, c1;
                __sincosf(p0, &s0, &c0);
                __sincosf(p1, &s1, &c1);
                c0 *= INV_SQRT_R; s0 *= INV_SQRT_R;
                c1 *= INV_SQRT_R; s1 *= INV_SQRT_R;
                bf16 ch0, cl0, ch1, cl1, sh0, sl0, sh1, sl1;
                bsplit(c0, ch0, cl0); bsplit(c1, ch1, cl1);
                bsplit(s0, sh0, sl0); bsplit(s1, sh1, sl1);
                if (qk == 0) {
                    size_t base = ((size_t)bh * SEQ + n) * FEAT;
                    *(bf162*)&g_qfh[base + col]       = mk2(ch0, ch1);
                    *(bf162*)&g_qfl[base + col]       = mk2(cl0, cl1);
                    *(bf162*)&g_qfh[base + RFF + col] = mk2(sh0, sh1);
                    *(bf162*)&g_qfl[base + RFF + col] = mk2(sl0, sl1);
                } else {
                    size_t kb = ((size_t)bh * FEAT + col) * SEQ + n;
                    g_kfh[kb] = ch0;              g_kfl[kb] = cl0;
                    g_kfh[kb + SEQ] = ch1;        g_kfl[kb + SEQ] = cl1;
                    g_kfh[kb + (size_t)RFF*SEQ] = sh0;        g_kfl[kb + (size_t)RFF*SEQ] = sl0;
                    g_kfh[kb + (size_t)(RFF+1)*SEQ] = sh1;    g_kfl[kb + (size_t)(RFF+1)*SEQ] = sl1;
                }
            }
        }
    }
}

// ---------------- Kv GEMM (split-K) ----------------
#define KV_STG 28672
#define KV_SMEM (2 * KV_STG)

__global__ __launch_bounds__(256, 1) void gemm_kv()
{
    extern __shared__ __align__(128) char sm[];
    const int tid = threadIdx.x, wid = tid >> 5, lid = tid & 31;
    const int ks = blockIdx.x;
    const int bh = blockIdx.y >> 1, m2 = blockIdx.y & 1;
    const int wm = (wid & 3) * 32, wn = (wid >> 2) * 48;
    const uint32_t smb = smem_u32(sm);

    const bf16* Ah = g_kfh + ((size_t)bh * FEAT + m2 * 128) * SEQ + ks * 1024;
    const bf16* Al = g_kfl + ((size_t)bh * FEAT + m2 * 128) * SEQ + ks * 1024;
    const bf16* Bhp = g_vth + (size_t)bh * NPAD * SEQ + ks * 1024;
    const bf16* Blp = g_vtl + (size_t)bh * NPAD * SEQ + ks * 1024;

    float acc[2][6][4];
    #pragma unroll
    for (int i = 0; i < 2; i++)
        #pragma unroll
        for (int j = 0; j < 6; j++)
            #pragma unroll
            for (int e = 0; e < 4; e++) acc[i][j][e] = 0.f;

    auto load_stage = [&](int ci, int s) {
        const int k0 = ci * 32;
        const uint32_t sb = smb + s * KV_STG;
        #pragma unroll
        for (int it = 0; it < 2; it++) {
            int idx = tid + it * 256;
            int row = idx >> 2, q = idx & 3;
            uint32_t soff = row * 64 + ((q ^ ((row >> 1) & 3)) << 4);
            cpa16(sb + soff,        Ah + (size_t)row * SEQ + k0 + q * 8);
            cpa16(sb + 8192 + soff, Al + (size_t)row * SEQ + k0 + q * 8);
        }
        for (int idx = tid; idx < 384; idx += 256) {
            int row = idx >> 2, q = idx & 3;
            uint32_t soff = row * 64 + ((q ^ ((row >> 1) & 3)) << 4);
            cpa16(sb + 16384 + soff, Bhp + (size_t)row * SEQ + k0 + q * 8);
            cpa16(sb + 22528 + soff, Blp + (size_t)row * SEQ + k0 + q * 8);
        }
        cpa_commit();
    };

    load_stage(0, 0);
    #pragma unroll 1
    for (int ci = 0; ci < 32; ci++) {
        const int s = ci & 1;
        if (ci < 31) { load_stage(ci + 1, s ^ 1); asm volatile("cp.async.wait_group 1;"); }
        else         asm volatile("cp.async.wait_group 0;");
        __syncthreads();
        const uint32_t sb = smb + s * KV_STG;
        #pragma unroll
        for (int k2 = 0; k2 < 2; k2++) {
            uint32_t aH[2][4], aL[2][4], bH[6][2], bL[6][2];
            #pragma unroll
            for (int mi = 0; mi < 2; mi++) {
                int row = wm + mi * 16 + (lid & 7) + ((lid >> 3) & 1) * 8;
                int q = k2 * 2 + (lid >> 4);
                uint32_t off = row * 64 + ((q ^ ((row >> 1) & 3)) << 4);
                ldmx4(sb + off,        aH[mi][0], aH[mi][1], aH[mi][2], aH[mi][3]);
                ldmx4(sb + 8192 + off, aL[mi][0], aL[mi][1], aL[mi][2], aL[mi][3]);
            }
            #pragma unroll
            for (int np = 0; np < 3; np++) {
                int row = wn + np * 16 + (lid >> 4) * 8 + (lid & 7);
                int q = k2 * 2 + ((lid >> 3) & 1);
                uint32_t off = row * 64 + ((q ^ ((row >> 1) & 3)) << 4);
                ldmx4(sb + 16384 + off, bH[2*np][0], bH[2*np][1], bH[2*np+1][0], bH[2*np+1][1]);
                ldmx4(sb + 22528 + off, bL[2*np][0], bL[2*np][1], bL[2*np+1][0], bL[2*np+1][1]);
            }
            #pragma unroll
            for (int mi = 0; mi < 2; mi++)
                #pragma unroll
                for (int ni = 0; ni < 6; ni++)
                    mma16816(acc[mi][ni], aH[mi], bH[ni]);
            #pragma unroll
            for (int mi = 0; mi < 2; mi++)
                #pragma unroll
                for (int ni = 0; ni < 6; ni++)
                    mma16816(acc[mi][ni], aH[mi], bL[ni]);
            #pragma unroll
            for (int mi = 0; mi < 2; mi++)
                #pragma unroll
                for (int ni = 0; ni < 6; ni++)
                    mma16816(acc[mi][ni], aL[mi], bH[ni]);
        }
        __syncthreads();
    }

    const int g = lid >> 2, c2 = (lid & 3) * 2;
    #pragma unroll
    for (int mi = 0; mi < 2; mi++) {
        #pragma unroll
        for (int ni = 0; ni < 6; ni++) {
            int rl = wm + mi * 16 + g;
            int col = wn + ni * 8 + c2;
            float* dp = g_kvp + (((size_t)ks * BH + bh) * FEAT + m2 * 128 + rl) * NPAD + col;
            float2 o0 = { acc[mi][ni][0], acc[mi][ni][1] };
            float2 o1 = { acc[mi][ni][2], acc[mi][ni][3] };
            *(float2*)dp = o0;
            *(float2*)(dp + 8 * NPAD) = o1;
        }
    }
}

// ---------------- reduce partials + transpose + split ----------------
__global__ __launch_bounds__(256) void kv_reduce_t()
{
    int i = blockIdx.x * 256 + threadIdx.x;
    if (i >= BH * FEAT * NPAD) return;
    int bh = i / (FEAT * NPAD);
    int rem = i - bh * FEAT * NPAD;
    int f = rem / NPAD, d = rem - f * NPAD;
    float s = 0.f;
    #pragma unroll
    for (int ks = 0; ks < 8; ks++)
        s += g_kvp[(((size_t)ks * BH + bh) * FEAT + f) * NPAD + d];
    bf16 hi, lo; bsplit(s, hi, lo);
    g_dth[((size_t)bh * NPAD + d) * FEAT + f] = hi;
    g_dtl[((size_t)bh * NPAD + d) * FEAT + f] = lo;
}

// ---------------- out GEMM ----------------
#define OUT_SMEM (2 * KV_STG + 512)

__global__ __launch_bounds__(256, 1) void gemm_out()
{
    extern __shared__ __align__(128) char sm[];
    const int tid = threadIdx.x, wid = tid >> 5, lid = tid & 31;
    const int n0 = blockIdx.x * 128;
    const int bh = blockIdx.y;
    const int wm = (wid & 3) * 32, wn = (wid >> 2) * 48;
    const uint32_t smb = smem_u32(sm);
    float* sden = (float*)(sm + 2 * KV_STG);

    const bf16* Ah = g_qfh + ((size_t)bh * SEQ + n0) * FEAT;
    const bf16* Al = g_qfl + ((size_t)bh * SEQ + n0) * FEAT;
    const bf16* Bhp = g_dth + (size_t)bh * NPAD * FEAT;
    const bf16* Blp = g_dtl + (size_t)bh * NPAD * FEAT;

    float acc[2][6][4];
    #pragma unroll
    for (int i = 0; i < 2; i++)
        #pragma unroll
        for (int j = 0; j < 6; j++)
            #pragma unroll
            for (int e = 0; e < 4; e++) acc[i][j][e] = 0.f;

    auto load_stage = [&](int ci, int s) {
        const int k0 = ci * 32;
        const uint32_t sb = smb + s * KV_STG;
        #pragma unroll
        for (int it = 0; it < 2; it++) {
            int idx = tid + it * 256;
            int row = idx >> 2, q = idx & 3;
            uint32_t soff = row * 64 + ((q ^ ((row >> 1) & 3)) << 4);
            cpa16(sb + soff,        Ah + (size_t)row * FEAT + k0 + q * 8);
            cpa16(sb + 8192 + soff, Al + (size_t)row * FEAT + k0 + q * 8);
        }
        for (int idx = tid; idx < 384; idx += 256) {
            int row = idx >> 2, q = idx & 3;
            uint32_t soff = row * 64 + ((q ^ ((row >> 1) & 3)) << 4);
            cpa16(sb + 16384 + soff, Bhp + (size_t)row * FEAT + k0 + q * 8);
            cpa16(sb + 22528 + soff, Blp + (size_t)row * FEAT + k0 + q * 8);
        }
        cpa_commit();
    };

    load_stage(0, 0);
    #pragma unroll 1
    for (int ci = 0; ci < 8; ci++) {
        const int s = ci & 1;
        if (ci < 7) { load_stage(ci + 1, s ^ 1); asm volatile("cp.async.wait_group 1;"); }
        else        asm volatile("cp.async.wait_group 0;");
        __syncthreads();
        const uint32_t sb = smb + s * KV_STG;
        #pragma unroll
        for (int k2 = 0; k2 < 2; k2++) {
            uint32_t aH[2][4], aL[2][4], bH[6][2], bL[6][2];
            #pragma unroll
            for (int mi = 0; mi < 2; mi++) {
                int row = wm + mi * 16 + (lid & 7) + ((lid >> 3) & 1) * 8;
                int q = k2 * 2 + (lid >> 4);
                uint32_t off = row * 64 + ((q ^ ((row >> 1) & 3)) << 4);
                ldmx4(sb + off,        aH[mi][0], aH[mi][1], aH[mi][2], aH[mi][3]);
                ldmx4(sb + 8192 + off, aL[mi][0], aL[mi][1], aL[mi][2], aL[mi][3]);
            }
            #pragma unroll
            for (int np = 0; np < 3; np++) {
                int row = wn + np * 16 + (lid >> 4) * 8 + (lid & 7);
                int q = k2 * 2 + ((lid >> 3) & 1);
                uint32_t off = row * 64 + ((q ^ ((row >> 1) & 3)) << 4);
                ldmx4(sb + 16384 + off, bH[2*np][0], bH[2*np][1], bH[2*np+1][0], bH[2*np+1][1]);
                ldmx4(sb + 22528 + off, bL[2*np][0], bL[2*np][1], bL[2*np+1][0], bL[2*np+1][1]);
            }
            #pragma unroll
            for (int mi = 0; mi < 2; mi++)
                #pragma unroll
                for (int ni = 0; ni < 6; ni++)
                    mma16816(acc[mi][ni], aH[mi], bH[ni]);
            #pragma unroll
            for (int mi = 0; mi < 2; mi++)
                #pragma unroll
                for (int ni = 0; ni < 6; ni++)
                    mma16816(acc[mi][ni], aH[mi], bL[ni]);
            #pragma unroll
            for (int mi = 0; mi < 2; mi++)
                #pragma unroll
                for (int ni = 0; ni < 6; ni++)
                    mma16816(acc[mi][ni], aL[mi], bH[ni]);
        }
        __syncthreads();
    }

    const int g = lid >> 2, c2 = (lid & 3) * 2;
    if ((wid >> 2) == 1 && (lid & 3) == 0) {
        #pragma unroll
        for (int mi = 0; mi < 2; mi++) {
            int rl = wm + mi * 16 + g;
            sden[rl]     = acc[mi][2][0];
            sden[rl + 8] = acc[mi][2][2];
        }
    }
    __syncthreads();

    const int b = bh >> 4, h = bh & 15;
    const int nlim = ((wid >> 2) == 0) ? 6 : 2;
    #pragma unroll
    for (int mi = 0; mi < 2; mi++) {
        int rl = wm + mi * 16 + g;
        float z0 = 1.f / (sden[rl] + 1e-6f);
        float z1 = 1.f / (sden[rl + 8] + 1e-6f);
        size_t rg0 = (size_t)(b * SEQ + n0 + rl) * DIMV + h * 64;
        size_t rg1 = rg0 + 8 * DIMV;
        for (int ni = 0; ni < nlim; ni++) {
            int col = wn + ni * 8 + c2;
            bf16 h0, l0, h1, l1;
            bsplit(acc[mi][ni][0] * z0, h0, l0); bsplit(acc[mi][ni][1] * z0, h1, l1);
            *(bf162*)&g_ah[rg0 + col] = mk2(h0, h1);
            *(bf162*)&g_al[rg0 + col] = mk2(l0, l1);
            bsplit(acc[mi][ni][2] * z1, h0, l0); bsplit(acc[mi][ni][3] * z1, h1, l1);
            *(bf162*)&g_ah[rg1 + col] = mk2(h0, h1);
            *(bf162*)&g_al[rg1 + col] = mk2(l0, l1);
        }
    }
}

// ---------------- launch ----------------
extern "C" void kernel_launch(void* const* d_in, const int* in_sizes, int n_in,
                              void* d_out, int out_size)
{
    const float* x  = (const float*)d_in[0];
    const float* Wq = (const float*)d_in[1];
    const float* Wk = (const float*)d_in[2];
    const float* Wv = (const float*)d_in[3];
    const float* Wp = (const float*)d_in[4];
    const float* bp = (const float*)d_in[5];
    const float* Wr = (const float*)d_in[6];
    const float* br = (const float*)d_in[7];
    float* out = (float*)d_out;

    bf16 *xh, *xl, *wh, *wl, *ah, *al;
    cudaGetSymbolAddress((void**)&xh, g_xh);   cudaGetSymbolAddress((void**)&xl, g_xl);
    cudaGetSymbolAddress((void**)&wh, g_wh);   cudaGetSymbolAddress((void**)&wl, g_wl);
    cudaGetSymbolAddress((void**)&ah, g_ah);   cudaGetSymbolAddress((void**)&al, g_al);

    cudaFuncSetAttribute(gemm3<0>, cudaFuncAttributeMaxDynamicSharedMemorySize, GEMM_SMEM);
    cudaFuncSetAttribute(gemm3<3>, cudaFuncAttributeMaxDynamicSharedMemorySize, GEMM_SMEM);
    cudaFuncSetAttribute(proj_feat, cudaFuncAttributeMaxDynamicSharedMemorySize, PROJ_SMEM);
    cudaFuncSetAttribute(gemm_kv,  cudaFuncAttributeMaxDynamicSharedMemorySize, KV_SMEM);
    cudaFuncSetAttribute(gemm_out, cudaFuncAttributeMaxDynamicSharedMemorySize, OUT_SMEM);

    const int WSZ = DIMV * DIMV;
    const int n4x = MROWS * DIMV / 4;
    const int n4w = WSZ / 4;

    split_bf16<<<(n4x + 255) / 256, 256>>>(x, xh, xl, n4x);
    split_bf16<<<(n4w + 255) / 256, 256>>>(Wq, wh + 0 * WSZ, wl + 0 * WSZ, n4w);
    split_bf16<<<(n4w + 255) / 256, 256>>>(Wk, wh + 1 * WSZ, wl + 1 * WSZ, n4w);
    split_bf16<<<(n4w + 255) / 256, 256>>>(Wv, wh + 2 * WSZ, wl + 2 * WSZ, n4w);
    split_bf16<<<(n4w + 255) / 256, 256>>>(Wp, wh + 3 * WSZ, wl + 3 * WSZ, n4w);
    prep_wrt<<<NHEADS, 256>>>(Wr);
    fill_vt<<<BH * 32, 256>>>();

    // merged QKV: N = 3072 (Wq, Wk, Wv stacked contiguously in g_wh/g_wl)
    gemm3<3><<<dim3(3 * DIMV / 128, MROWS / 128), 256, GEMM_SMEM>>>(
        xh, xl, wh, wl, nullptr, nullptr);

    proj_feat<<<dim3(MROWS / 128, 32), 256, PROJ_SMEM>>>(br);
    gemm_kv<<<dim3(8, BH * 2), 256, KV_SMEM>>>();
    kv_reduce_t<<<(BH * FEAT * NPAD + 255) / 256, 256>>>();
    gemm_out<<<dim3(SEQ / 128, BH), 256, OUT_SMEM>>>();

    gemm3<0><<<dim3(DIMV / 128, MROWS / 128), 256, GEMM_SMEM>>>(
        ah, al, wh + 3 * WSZ, wl + 3 * WSZ, bp, out);
}

// round 6
// speedup vs baseline: 1.4166x; 1.4166x over previous
#include <cuda_runtime.h>
#include <cuda_bf16.h>
#include <math.h>
#include <stdint.h>

#define DIMV 1024
#define NHEADS 16
#define DK 64
#define RFF 128
#define FEAT 256
#define BATCH 2
#define SEQ 8192
#define MROWS 16384
#define BH 32
#define NPAD 96
#define INV_SQRT_R 0.08838834764831845f

typedef __nv_bfloat16 bf16;
typedef __nv_bfloat162 bf162;

// ---------------- scratch (device globals) ----------------
__device__ int8_t g_xq1[MROWS*DIMV], g_xq2[MROWS*DIMV];
__device__ float  g_sx[MROWS];
__device__ int8_t g_wq1[3*DIMV*DIMV], g_wq2[3*DIMV*DIMV];
__device__ float  g_sw[3*DIMV];
__device__ int8_t g_pq1[DIMV*DIMV], g_pq2[DIMV*DIMV];
__device__ float  g_sp[DIMV];
__device__ bf16 g_qh[MROWS*DIMV], g_ql[MROWS*DIMV];
__device__ bf16 g_kh[MROWS*DIMV], g_kl[MROWS*DIMV];
__device__ bf16 g_vth[BH*NPAD*SEQ], g_vtl[BH*NPAD*SEQ];
__device__ bf16 g_wrth[NHEADS*RFF*DK], g_wrtl[NHEADS*RFF*DK];
__device__ bf16 g_qfh[(size_t)BH*SEQ*FEAT], g_qfl[(size_t)BH*SEQ*FEAT];
__device__ bf16 g_kfh[(size_t)BH*FEAT*SEQ], g_kfl[(size_t)BH*FEAT*SEQ];
__device__ float g_kvp[8*BH*FEAT*NPAD];
__device__ bf16 g_dth[BH*NPAD*FEAT], g_dtl[BH*NPAD*FEAT];
__device__ float g_af[MROWS*DIMV];
__device__ int8_t g_aq1[MROWS*DIMV], g_aq2[MROWS*DIMV];
__device__ float  g_sa[MROWS];

// ---------------- helpers ----------------
__device__ __forceinline__ uint32_t smem_u32(const void* p) {
    uint32_t a;
    asm("{ .reg .u64 t; cvta.to.shared.u64 t, %1; cvt.u32.u64 %0, t; }" : "=r"(a) : "l"(p));
    return a;
}
__device__ __forceinline__ void cpa16(uint32_t s, const void* g) {
    asm volatile("cp.async.cg.shared.global [%0], [%1], 16;" :: "r"(s), "l"(g));
}
__device__ __forceinline__ void cpa_commit() { asm volatile("cp.async.commit_group;"); }
__device__ __forceinline__ void ldmx4(uint32_t addr, uint32_t& r0, uint32_t& r1, uint32_t& r2, uint32_t& r3) {
    asm volatile("ldmatrix.sync.aligned.m8n8.x4.shared.b16 {%0,%1,%2,%3}, [%4];"
                 : "=r"(r0), "=r"(r1), "=r"(r2), "=r"(r3) : "r"(addr));
}
__device__ __forceinline__ void mma16816(float* d, const uint32_t* a, const uint32_t* b) {
    asm volatile(
        "mma.sync.aligned.m16n8k16.row.col.f32.bf16.bf16.f32 "
        "{%0,%1,%2,%3}, {%4,%5,%6,%7}, {%8,%9}, {%0,%1,%2,%3};"
        : "+f"(d[0]), "+f"(d[1]), "+f"(d[2]), "+f"(d[3])
        : "r"(a[0]), "r"(a[1]), "r"(a[2]), "r"(a[3]), "r"(b[0]), "r"(b[1]));
}
__device__ __forceinline__ void imma16832(int* d, const uint32_t* a, const uint32_t* b) {
    asm volatile(
        "mma.sync.aligned.m16n8k32.row.col.s32.s8.s8.s32 "
        "{%0,%1,%2,%3}, {%4,%5,%6,%7}, {%8,%9}, {%0,%1,%2,%3};"
        : "+r"(d[0]), "+r"(d[1]), "+r"(d[2]), "+r"(d[3])
        : "r"(a[0]), "r"(a[1]), "r"(a[2]), "r"(a[3]), "r"(b[0]), "r"(b[1]));
}
__device__ __forceinline__ void bsplit(float v, bf16& h, bf16& l) {
    h = __float2bfloat16(v);
    l = __float2bfloat16(v - __bfloat162float(h));
}
__device__ __forceinline__ bf162 mk2(bf16 a, bf16 b) { bf162 t; t.x = a; t.y = b; return t; }

// ---------------- per-row 2-digit int8 quantization (warp per row, K=1024) ----------------
__global__ __launch_bounds__(256) void quant_rows(
    const float* __restrict__ in, int8_t* __restrict__ q1,
    int8_t* __restrict__ q2, float* __restrict__ sc, int nrows)
{
    int row = blockIdx.x * 8 + (threadIdx.x >> 5);
    if (row >= nrows) return;
    int lid = threadIdx.x & 31;
    const float4* r = (const float4*)(in + (size_t)row * 1024);
    float4 v[8];
    float mx = 0.f;
    #pragma unroll
    for (int i = 0; i < 8; i++) {
        v[i] = r[lid + 32 * i];
        mx = fmaxf(mx, fmaxf(fmaxf(fabsf(v[i].x), fabsf(v[i].y)),
                             fmaxf(fabsf(v[i].z), fabsf(v[i].w))));
    }
    #pragma unroll
    for (int o = 16; o; o >>= 1) mx = fmaxf(mx, __shfl_xor_sync(0xFFFFFFFFu, mx, o));
    mx = fmaxf(mx, 1e-20f);
    float inv = 127.f / mx;
    if (lid == 0) sc[row] = mx / 127.f;
    char4* o1 = (char4*)(q1 + (size_t)row * 1024);
    char4* o2 = (char4*)(q2 + (size_t)row * 1024);
    #pragma unroll
    for (int i = 0; i < 8; i++) {
        float qv[4] = { v[i].x * inv, v[i].y * inv, v[i].z * inv, v[i].w * inv };
        char c1[4], c2[4];
        #pragma unroll
        for (int j = 0; j < 4; j++) {
            float a1 = rintf(qv[j]);
            float r2 = (qv[j] - a1) * 256.f;
            float a2 = fminf(fmaxf(rintf(r2), -127.f), 127.f);
            c1[j] = (char)a1; c2[j] = (char)a2;
        }
        o1[lid + 32 * i] = make_char4(c1[0], c1[1], c1[2], c1[3]);
        o2[lid + 32 * i] = make_char4(c2[0], c2[1], c2[2], c2[3]);
    }
}

// ---------------- WrT prep ----------------
__global__ __launch_bounds__(256) void prep_wrt(const float* __restrict__ Wr)
{
    int h = blockIdx.x;
    for (int e = threadIdx.x; e < RFF * DK; e += 256) {
        int r = e >> 6, j = e & 63;
        float v = Wr[(size_t)h * DK * RFF + j * RFF + r];
        bf16 hi, lo; bsplit(v, hi, lo);
        g_wrth[h * RFF * DK + e] = hi;
        g_wrtl[h * RFF * DK + e] = lo;
    }
}

// ---------------- vT padding rows ----------------
__global__ __launch_bounds__(256) void fill_vt()
{
    int bx = blockIdx.x;
    int bh = bx >> 5, dr = 64 + (bx & 31);
    bf16 v = __float2bfloat16(dr == 64 ? 1.f : 0.f);
    bf16 z = __float2bfloat16(0.f);
    bf162 vv = mk2(v, v), zz = mk2(z, z);
    size_t base = ((size_t)bh * NPAD + dr) * SEQ;
    for (int i = threadIdx.x; i < SEQ / 2; i += 256) {
        *(bf162*)&g_vth[base + 2 * i] = vv;
        *(bf162*)&g_vtl[base + 2 * i] = zz;
    }
}

// ---------------- int8x2 IMMA GEMM: C[M,N] = A @ B^T ----------------
// 128x128 CTA tile, 8 warps (2x4, 64x32 warp tiles), BK=64 int8, 2-stage cp.async.
// SMEM stage: A1[128x64] A2 B1 B2 (8KB each, 32KB/stage).
// MODE 0: dequant + bias -> fp32 C. MODE 3: merged QKV (N=3072) -> q/k bf16 hi/lo, vT.
#define ISTG 32768
#define IGEMM_SMEM (2 * ISTG)

template<int MODE>
__global__ __launch_bounds__(256, 1) void gemm_i8(
    const int8_t* __restrict__ A1, const int8_t* __restrict__ A2, const float* __restrict__ sA,
    const int8_t* __restrict__ B1, const int8_t* __restrict__ B2, const float* __restrict__ sB,
    const float* __restrict__ bias, float* __restrict__ C)
{
    extern __shared__ __align__(128) char sm[];
    const int tid = threadIdx.x, wid = tid >> 5, lid = tid & 31;
    const int m0 = blockIdx.y * 128, n0 = blockIdx.x * 128;
    const int wm = (wid & 1) * 64;
    const int wn = (wid >> 1) * 32;
    const uint32_t smb = smem_u32(sm);

    int X[4][4][4], Y[4][4][4];
    #pragma unroll
    for (int i = 0; i < 4; i++)
        #pragma unroll
        for (int j = 0; j < 4; j++)
            #pragma unroll
            for (int e = 0; e < 4; e++) { X[i][j][e] = 0; Y[i][j][e] = 0; }

    auto load_stage = [&](int ci, int s) {
        const int k0 = ci * 64;
        const uint32_t sb = smb + s * ISTG;
        #pragma unroll
        for (int it = 0; it < 2; it++) {
            int t = tid + it * 256;
            int row = t >> 2, q = t & 3;
            uint32_t soff = row * 64 + ((q ^ ((row >> 1) & 3)) << 4);
            size_t ga = (size_t)(m0 + row) * DIMV + k0 + q * 16;
            size_t gb = (size_t)(n0 + row) * DIMV + k0 + q * 16;
            cpa16(sb + soff,         A1 + ga);
            cpa16(sb + 8192  + soff, A2 + ga);
            cpa16(sb + 16384 + soff, B1 + gb);
            cpa16(sb + 24576 + soff, B2 + gb);
        }
        cpa_commit();
    };

    load_stage(0, 0);

    #pragma unroll 1
    for (int ci = 0; ci < 16; ci++) {
        const int s = ci & 1;
        if (ci < 15) { load_stage(ci + 1, s ^ 1); asm volatile("cp.async.wait_group 1;"); }
        else         asm volatile("cp.async.wait_group 0;");
        __syncthreads();

        const uint32_t sb = smb + s * ISTG;
        #pragma unroll
        for (int ks = 0; ks < 2; ks++) {
            uint32_t a1f[4][4], a2f[4][4], b1f[4][2], b2f[4][2];
            #pragma unroll
            for (int mi = 0; mi < 4; mi++) {
                int row = wm + mi * 16 + (lid & 7) + ((lid >> 3) & 1) * 8;
                int q = ks * 2 + (lid >> 4);
                uint32_t off = row * 64 + ((q ^ ((row >> 1) & 3)) << 4);
                ldmx4(sb + off,        a1f[mi][0], a1f[mi][1], a1f[mi][2], a1f[mi][3]);
                ldmx4(sb + 8192 + off, a2f[mi][0], a2f[mi][1], a2f[mi][2], a2f[mi][3]);
            }
            #pragma unroll
            for (int np = 0; np < 2; np++) {
                int row = wn + np * 16 + (lid >> 4) * 8 + (lid & 7);
                int q = ks * 2 + ((lid >> 3) & 1);
                uint32_t off = row * 64 + ((q ^ ((row >> 1) & 3)) << 4);
                ldmx4(sb + 16384 + off, b1f[2*np][0], b1f[2*np][1], b1f[2*np+1][0], b1f[2*np+1][1]);
                ldmx4(sb + 24576 + off, b2f[2*np][0], b2f[2*np][1], b2f[2*np+1][0], b2f[2*np+1][1]);
            }
            #pragma unroll
            for (int mi = 0; mi < 4; mi++)
                #pragma unroll
                for (int ni = 0; ni < 4; ni++)
                    imma16832(X[mi][ni], a1f[mi], b1f[ni]);
            #pragma unroll
            for (int mi = 0; mi < 4; mi++)
                #pragma unroll
                for (int ni = 0; ni < 4; ni++)
                    imma16832(Y[mi][ni], a1f[mi], b2f[ni]);
            #pragma unroll
            for (int mi = 0; mi < 4; mi++)
                #pragma unroll
                for (int ni = 0; ni < 4; ni++)
                    imma16832(Y[mi][ni], a2f[mi], b1f[ni]);
        }
        __syncthreads();
    }

    const int g = lid >> 2, c2 = (lid & 3) * 2;
    #pragma unroll
    for (int mi = 0; mi < 4; mi++) {
        int row = m0 + wm + mi * 16 + g;
        float sa0 = sA[row], sa1 = sA[row + 8];
        #pragma unroll
        for (int ni = 0; ni < 4; ni++) {
            int col = n0 + wn + ni * 8 + c2;
            float sb0 = sB[col], sb1 = sB[col + 1];
            float r00 = sa0 * sb0 * ((float)X[mi][ni][0] + (float)Y[mi][ni][0] * (1.f/256.f));
            float r01 = sa0 * sb1 * ((float)X[mi][ni][1] + (float)Y[mi][ni][1] * (1.f/256.f));
            float r10 = sa1 * sb0 * ((float)X[mi][ni][2] + (float)Y[mi][ni][2] * (1.f/256.f));
            float r11 = sa1 * sb1 * ((float)X[mi][ni][3] + (float)Y[mi][ni][3] * (1.f/256.f));
            if (MODE == 0) {
                float b0 = bias ? bias[col] : 0.f;
                float b1 = bias ? bias[col + 1] : 0.f;
                float2 o0 = { r00 + b0, r01 + b1 };
                float2 o1 = { r10 + b0, r11 + b1 };
                *(float2*)&C[(size_t)row * DIMV + col]       = o0;
                *(float2*)&C[(size_t)(row + 8) * DIMV + col] = o1;
            } else {
                if (col < 2048) {
                    bf16* Ch = (col < 1024) ? g_qh : g_kh;
                    bf16* Cl = (col < 1024) ? g_ql : g_kl;
                    int cc = col & 1023;
                    bf16 h0, l0, h1, l1;
                    bsplit(r00, h0, l0); bsplit(r01, h1, l1);
                    *(bf162*)&Ch[(size_t)row * DIMV + cc] = mk2(h0, h1);
                    *(bf162*)&Cl[(size_t)row * DIMV + cc] = mk2(l0, l1);
                    bsplit(r10, h0, l0); bsplit(r11, h1, l1);
                    *(bf162*)&Ch[(size_t)(row + 8) * DIMV + cc] = mk2(h0, h1);
                    *(bf162*)&Cl[(size_t)(row + 8) * DIMV + cc] = mk2(l0, l1);
                } else {
                    int cc = col - 2048;
                    int hh = cc >> 6, d0 = cc & 63;
                    int b = row >> 13, n = row & 8191;
                    size_t base = ((size_t)(b * NHEADS + hh) * NPAD) * SEQ;
                    bf16 h0, l0;
                    bsplit(r00, h0, l0);
                    g_vth[base + (size_t)d0 * SEQ + n] = h0;       g_vtl[base + (size_t)d0 * SEQ + n] = l0;
                    bsplit(r01, h0, l0);
                    g_vth[base + (size_t)(d0+1) * SEQ + n] = h0;   g_vtl[base + (size_t)(d0+1) * SEQ + n] = l0;
                    bsplit(r10, h0, l0);
                    g_vth[base + (size_t)d0 * SEQ + n + 8] = h0;   g_vtl[base + (size_t)d0 * SEQ + n + 8] = l0;
                    bsplit(r11, h0, l0);
                    g_vth[base + (size_t)(d0+1) * SEQ + n + 8] = h0; g_vtl[base + (size_t)(d0+1) * SEQ + n + 8] = l0;
                }
            }
        }
    }
}

// ---------------- proj + RFF features ----------------
#define PROJ_SMEM 65536

__global__ __launch_bounds__(256, 1) void proj_feat(const float* __restrict__ brp)
{
    extern __shared__ __align__(128) char sm[];
    const int tid = threadIdx.x, wid = tid >> 5, lid = tid & 31;
    const int m0 = blockIdx.x * 128;
    const int qk = blockIdx.y >> 4, h = blockIdx.y & 15;
    const int wm = (wid & 1) * 64, wn = (wid >> 1) * 32;
    const uint32_t smb = smem_u32(sm);

    const bf16* Ah = (qk ? g_kh : g_qh);
    const bf16* Al = (qk ? g_kl : g_ql);
    const bf16* Bh = g_wrth + h * RFF * DK;
    const bf16* Bl = g_wrtl + h * RFF * DK;

    #pragma unroll
    for (int it = 0; it < 4; it++) {
        int idx = tid + it * 256;
        int row = idx >> 3, q = idx & 7;
        uint32_t soff = row * 128 + ((q ^ (row & 7)) << 4);
        *(uint4*)(sm + soff)         = *(const uint4*)(Ah + (size_t)(m0 + row) * DIMV + h * DK + q * 8);
        *(uint4*)(sm + 16384 + soff) = *(const uint4*)(Al + (size_t)(m0 + row) * DIMV + h * DK + q * 8);
        *(uint4*)(sm + 32768 + soff) = *(const uint4*)(Bh + row * DK + q * 8);
        *(uint4*)(sm + 49152 + soff) = *(const uint4*)(Bl + row * DK + q * 8);
    }
    __syncthreads();

    float acc[4][4][4];
    #pragma unroll
    for (int i = 0; i < 4; i++)
        #pragma unroll
        for (int j = 0; j < 4; j++)
            #pragma unroll
            for (int e = 0; e < 4; e++) acc[i][j][e] = 0.f;

    #pragma unroll
    for (int ks = 0; ks < 4; ks++) {
        uint32_t aH[4][4], aL[4][4], bH[4][2], bL[4][2];
        #pragma unroll
        for (int mi = 0; mi < 4; mi++) {
            int row = wm + mi * 16 + (lid & 7) + ((lid >> 3) & 1) * 8;
            int q = ks * 2 + (lid >> 4);
            uint32_t off = row * 128 + ((q ^ (row & 7)) << 4);
            ldmx4(smb + off,         aH[mi][0], aH[mi][1], aH[mi][2], aH[mi][3]);
            ldmx4(smb + 16384 + off, aL[mi][0], aL[mi][1], aL[mi][2], aL[mi][3]);
        }
        #pragma unroll
        for (int np = 0; np < 2; np++) {
            int row = wn + np * 16 + (lid >> 4) * 8 + (lid & 7);
            int q = ks * 2 + ((lid >> 3) & 1);
            uint32_t off = row * 128 + ((q ^ (row & 7)) << 4);
            ldmx4(smb + 32768 + off, bH[2*np][0], bH[2*np][1], bH[2*np+1][0], bH[2*np+1][1]);
            ldmx4(smb + 49152 + off, bL[2*np][0], bL[2*np][1], bL[2*np+1][0], bL[2*np+1][1]);
        }
        #pragma unroll
        for (int mi = 0; mi < 4; mi++)
            #pragma unroll
            for (int ni = 0; ni < 4; ni++)
                mma16816(acc[mi][ni], aH[mi], bH[ni]);
        #pragma unroll
        for (int mi = 0; mi < 4; mi++)
            #pragma unroll
            for (int ni = 0; ni < 4; ni++)
                mma16816(acc[mi][ni], aH[mi], bL[ni]);
        #pragma unroll
        for (int mi = 0; mi < 4; mi++)
            #pragma unroll
            for (int ni = 0; ni < 4; ni++)
                mma16816(acc[mi][ni], aL[mi], bH[ni]);
    }

    const int g = lid >> 2, c2 = (lid & 3) * 2;
    #pragma unroll
    for (int mi = 0; mi < 4; mi++) {
        #pragma unroll
        for (int ni = 0; ni < 4; ni++) {
            int col = wn + ni * 8 + c2;
            float b0 = brp[h * RFF + col], b1 = brp[h * RFF + col + 1];
            #pragma unroll
            for (int half = 0; half < 2; half++) {
                int row = m0 + wm + mi * 16 + g + half * 8;
                int b = row >> 13, n = row & 8191;
                int bh = b * NHEADS + h;
                float p0 = acc[mi][ni][half * 2 + 0] + b0;
                float p1 = acc[mi][ni][half * 2 + 1] + b1;
                float s0, c0, s1, c1;
                __sincosf(p0, &s0, &c0);
                __sincosf(p1, &s1, &c1);
                c0 *= INV_SQRT_R; s0 *= INV_SQRT_R;
                c1 *= INV_SQRT_R; s1 *= INV_SQRT_R;
                bf16 ch0, cl0, ch1, cl1, sh0, sl0, sh1, sl1;
                bsplit(c0, ch0, cl0); bsplit(c1, ch1, cl1);
                bsplit(s0, sh0, sl0); bsplit(s1, sh1, sl1);
                if (qk == 0) {
                    size_t base = ((size_t)bh * SEQ + n) * FEAT;
                    *(bf162*)&g_qfh[base + col]       = mk2(ch0, ch1);
                    *(bf162*)&g_qfl[base + col]       = mk2(cl0, cl1);
                    *(bf162*)&g_qfh[base + RFF + col] = mk2(sh0, sh1);
                    *(bf162*)&g_qfl[base + RFF + col] = mk2(sl0, sl1);
                } else {
                    size_t kb = ((size_t)bh * FEAT + col) * SEQ + n;
                    g_kfh[kb] = ch0;              g_kfl[kb] = cl0;
                    g_kfh[kb + SEQ] = ch1;        g_kfl[kb + SEQ] = cl1;
                    g_kfh[kb + (size_t)RFF*SEQ] = sh0;        g_kfl[kb + (size_t)RFF*SEQ] = sl0;
                    g_kfh[kb + (size_t)(RFF+1)*SEQ] = sh1;    g_kfl[kb + (size_t)(RFF+1)*SEQ] = sl1;
                }
            }
        }
    }
}

// ---------------- Kv GEMM (split-K) ----------------
#define KV_STG 28672
#define KV_SMEM (2 * KV_STG)

__global__ __launch_bounds__(256, 1) void gemm_kv()
{
    extern __shared__ __align__(128) char sm[];
    const int tid = threadIdx.x, wid = tid >> 5, lid = tid & 31;
    const int ks = blockIdx.x;
    const int bh = blockIdx.y >> 1, m2 = blockIdx.y & 1;
    const int wm = (wid & 3) * 32, wn = (wid >> 2) * 48;
    const uint32_t smb = smem_u32(sm);

    const bf16* Ah = g_kfh + ((size_t)bh * FEAT + m2 * 128) * SEQ + ks * 1024;
    const bf16* Al = g_kfl + ((size_t)bh * FEAT + m2 * 128) * SEQ + ks * 1024;
    const bf16* Bhp = g_vth + (size_t)bh * NPAD * SEQ + ks * 1024;
    const bf16* Blp = g_vtl + (size_t)bh * NPAD * SEQ + ks * 1024;

    float acc[2][6][4];
    #pragma unroll
    for (int i = 0; i < 2; i++)
        #pragma unroll
        for (int j = 0; j < 6; j++)
            #pragma unroll
            for (int e = 0; e < 4; e++) acc[i][j][e] = 0.f;

    auto load_stage = [&](int ci, int s) {
        const int k0 = ci * 32;
        const uint32_t sb = smb + s * KV_STG;
        #pragma unroll
        for (int it = 0; it < 2; it++) {
            int idx = tid + it * 256;
            int row = idx >> 2, q = idx & 3;
            uint32_t soff = row * 64 + ((q ^ ((row >> 1) & 3)) << 4);
            cpa16(sb + soff,        Ah + (size_t)row * SEQ + k0 + q * 8);
            cpa16(sb + 8192 + soff, Al + (size_t)row * SEQ + k0 + q * 8);
        }
        for (int idx = tid; idx < 384; idx += 256) {
            int row = idx >> 2, q = idx & 3;
            uint32_t soff = row * 64 + ((q ^ ((row >> 1) & 3)) << 4);
            cpa16(sb + 16384 + soff, Bhp + (size_t)row * SEQ + k0 + q * 8);
            cpa16(sb + 22528 + soff, Blp + (size_t)row * SEQ + k0 + q * 8);
        }
        cpa_commit();
    };

    load_stage(0, 0);
    #pragma unroll 1
    for (int ci = 0; ci < 32; ci++) {
        const int s = ci & 1;
        if (ci < 31) { load_stage(ci + 1, s ^ 1); asm volatile("cp.async.wait_group 1;"); }
        else         asm volatile("cp.async.wait_group 0;");
        __syncthreads();
        const uint32_t sb = smb + s * KV_STG;
        #pragma unroll
        for (int k2 = 0; k2 < 2; k2++) {
            uint32_t aH[2][4], aL[2][4], bH[6][2], bL[6][2];
            #pragma unroll
            for (int mi = 0; mi < 2; mi++) {
                int row = wm + mi * 16 + (lid & 7) + ((lid >> 3) & 1) * 8;
                int q = k2 * 2 + (lid >> 4);
                uint32_t off = row * 64 + ((q ^ ((row >> 1) & 3)) << 4);
                ldmx4(sb + off,        aH[mi][0], aH[mi][1], aH[mi][2], aH[mi][3]);
                ldmx4(sb + 8192 + off, aL[mi][0], aL[mi][1], aL[mi][2], aL[mi][3]);
            }
            #pragma unroll
            for (int np = 0; np < 3; np++) {
                int row = wn + np * 16 + (lid >> 4) * 8 + (lid & 7);
                int q = k2 * 2 + ((lid >> 3) & 1);
                uint32_t off = row * 64 + ((q ^ ((row >> 1) & 3)) << 4);
                ldmx4(sb + 16384 + off, bH[2*np][0], bH[2*np][1], bH[2*np+1][0], bH[2*np+1][1]);
                ldmx4(sb + 22528 + off, bL[2*np][0], bL[2*np][1], bL[2*np+1][0], bL[2*np+1][1]);
            }
            #pragma unroll
            for (int mi = 0; mi < 2; mi++)
                #pragma unroll
                for (int ni = 0; ni < 6; ni++)
                    mma16816(acc[mi][ni], aH[mi], bH[ni]);
            #pragma unroll
            for (int mi = 0; mi < 2; mi++)
                #pragma unroll
                for (int ni = 0; ni < 6; ni++)
                    mma16816(acc[mi][ni], aH[mi], bL[ni]);
            #pragma unroll
            for (int mi = 0; mi < 2; mi++)
                #pragma unroll
                for (int ni = 0; ni < 6; ni++)
                    mma16816(acc[mi][ni], aL[mi], bH[ni]);
        }
        __syncthreads();
    }

    const int g = lid >> 2, c2 = (lid & 3) * 2;
    #pragma unroll
    for (int mi = 0; mi < 2; mi++) {
        #pragma unroll
        for (int ni = 0; ni < 6; ni++) {
            int rl = wm + mi * 16 + g;
            int col = wn + ni * 8 + c2;
            float* dp = g_kvp + (((size_t)ks * BH + bh) * FEAT + m2 * 128 + rl) * NPAD + col;
            float2 o0 = { acc[mi][ni][0], acc[mi][ni][1] };
            float2 o1 = { acc[mi][ni][2], acc[mi][ni][3] };
            *(float2*)dp = o0;
            *(float2*)(dp + 8 * NPAD) = o1;
        }
    }
}

// ---------------- reduce partials + transpose + split ----------------
__global__ __launch_bounds__(256) void kv_reduce_t()
{
    int i = blockIdx.x * 256 + threadIdx.x;
    if (i >= BH * FEAT * NPAD) return;
    int bh = i / (FEAT * NPAD);
    int rem = i - bh * FEAT * NPAD;
    int f = rem / NPAD, d = rem - f * NPAD;
    float s = 0.f;
    #pragma unroll
    for (int ks = 0; ks < 8; ks++)
        s += g_kvp[(((size_t)ks * BH + bh) * FEAT + f) * NPAD + d];
    bf16 hi, lo; bsplit(s, hi, lo);
    g_dth[((size_t)bh * NPAD + d) * FEAT + f] = hi;
    g_dtl[((size_t)bh * NPAD + d) * FEAT + f] = lo;
}

// ---------------- out GEMM ----------------
#define OUT_SMEM (2 * KV_STG + 512)

__global__ __launch_bounds__(256, 1) void gemm_out()
{
    extern __shared__ __align__(128) char sm[];
    const int tid = threadIdx.x, wid = tid >> 5, lid = tid & 31;
    const int n0 = blockIdx.x * 128;
    const int bh = blockIdx.y;
    const int wm = (wid & 3) * 32, wn = (wid >> 2) * 48;
    const uint32_t smb = smem_u32(sm);
    float* sden = (float*)(sm + 2 * KV_STG);

    const bf16* Ah = g_qfh + ((size_t)bh * SEQ + n0) * FEAT;
    const bf16* Al = g_qfl + ((size_t)bh * SEQ + n0) * FEAT;
    const bf16* Bhp = g_dth + (size_t)bh * NPAD * FEAT;
    const bf16* Blp = g_dtl + (size_t)bh * NPAD * FEAT;

    float acc[2][6][4];
    #pragma unroll
    for (int i = 0; i < 2; i++)
        #pragma unroll
        for (int j = 0; j < 6; j++)
            #pragma unroll
            for (int e = 0; e < 4; e++) acc[i][j][e] = 0.f;

    auto load_stage = [&](int ci, int s) {
        const int k0 = ci * 32;
        const uint32_t sb = smb + s * KV_STG;
        #pragma unroll
        for (int it = 0; it < 2; it++) {
            int idx = tid + it * 256;
            int row = idx >> 2, q = idx & 3;
            uint32_t soff = row * 64 + ((q ^ ((row >> 1) & 3)) << 4);
            cpa16(sb + soff,        Ah + (size_t)row * FEAT + k0 + q * 8);
            cpa16(sb + 8192 + soff, Al + (size_t)row * FEAT + k0 + q * 8);
        }
        for (int idx = tid; idx < 384; idx += 256) {
            int row = idx >> 2, q = idx & 3;
            uint32_t soff = row * 64 + ((q ^ ((row >> 1) & 3)) << 4);
            cpa16(sb + 16384 + soff, Bhp + (size_t)row * FEAT + k0 + q * 8);
            cpa16(sb + 22528 + soff, Blp + (size_t)row * FEAT + k0 + q * 8);
        }
        cpa_commit();
    };

    load_stage(0, 0);
    #pragma unroll 1
    for (int ci = 0; ci < 8; ci++) {
        const int s = ci & 1;
        if (ci < 7) { load_stage(ci + 1, s ^ 1); asm volatile("cp.async.wait_group 1;"); }
        else        asm volatile("cp.async.wait_group 0;");
        __syncthreads();
        const uint32_t sb = smb + s * KV_STG;
        #pragma unroll
        for (int k2 = 0; k2 < 2; k2++) {
            uint32_t aH[2][4], aL[2][4], bH[6][2], bL[6][2];
            #pragma unroll
            for (int mi = 0; mi < 2; mi++) {
                int row = wm + mi * 16 + (lid & 7) + ((lid >> 3) & 1) * 8;
                int q = k2 * 2 + (lid >> 4);
                uint32_t off = row * 64 + ((q ^ ((row >> 1) & 3)) << 4);
                ldmx4(sb + off,        aH[mi][0], aH[mi][1], aH[mi][2], aH[mi][3]);
                ldmx4(sb + 8192 + off, aL[mi][0], aL[mi][1], aL[mi][2], aL[mi][3]);
            }
            #pragma unroll
            for (int np = 0; np < 3; np++) {
                int row = wn + np * 16 + (lid >> 4) * 8 + (lid & 7);
                int q = k2 * 2 + ((lid >> 3) & 1);
                uint32_t off = row * 64 + ((q ^ ((row >> 1) & 3)) << 4);
                ldmx4(sb + 16384 + off, bH[2*np][0], bH[2*np][1], bH[2*np+1][0], bH[2*np+1][1]);
                ldmx4(sb + 22528 + off, bL[2*np][0], bL[2*np][1], bL[2*np+1][0], bL[2*np+1][1]);
            }
            #pragma unroll
            for (int mi = 0; mi < 2; mi++)
                #pragma unroll
                for (int ni = 0; ni < 6; ni++)
                    mma16816(acc[mi][ni], aH[mi], bH[ni]);
            #pragma unroll
            for (int mi = 0; mi < 2; mi++)
                #pragma unroll
                for (int ni = 0; ni < 6; ni++)
                    mma16816(acc[mi][ni], aH[mi], bL[ni]);
            #pragma unroll
            for (int mi = 0; mi < 2; mi++)
                #pragma unroll
                for (int ni = 0; ni < 6; ni++)
                    mma16816(acc[mi][ni], aL[mi], bH[ni]);
        }
        __syncthreads();
    }

    const int g = lid >> 2, c2 = (lid & 3) * 2;
    if ((wid >> 2) == 1 && (lid & 3) == 0) {
        #pragma unroll
        for (int mi = 0; mi < 2; mi++) {
            int rl = wm + mi * 16 + g;
            sden[rl]     = acc[mi][2][0];
            sden[rl + 8] = acc[mi][2][2];
        }
    }
    __syncthreads();

    const int b = bh >> 4, h = bh & 15;
    const int nlim = ((wid >> 2) == 0) ? 6 : 2;
    #pragma unroll
    for (int mi = 0; mi < 2; mi++) {
        int rl = wm + mi * 16 + g;
        float z0 = 1.f / (sden[rl] + 1e-6f);
        float z1 = 1.f / (sden[rl + 8] + 1e-6f);
        size_t rg0 = (size_t)(b * SEQ + n0 + rl) * DIMV + h * 64;
        size_t rg1 = rg0 + 8 * DIMV;
        for (int ni = 0; ni < nlim; ni++) {
            int col = wn + ni * 8 + c2;
            float2 o0 = { acc[mi][ni][0] * z0, acc[mi][ni][1] * z0 };
            float2 o1 = { acc[mi][ni][2] * z1, acc[mi][ni][3] * z1 };
            *(float2*)&g_af[rg0 + col] = o0;
            *(float2*)&g_af[rg1 + col] = o1;
        }
    }
}

// ---------------- launch ----------------
extern "C" void kernel_launch(void* const* d_in, const int* in_sizes, int n_in,
                              void* d_out, int out_size)
{
    const float* x  = (const float*)d_in[0];
    const float* Wq = (const float*)d_in[1];
    const float* Wk = (const float*)d_in[2];
    const float* Wv = (const float*)d_in[3];
    const float* Wp = (const float*)d_in[4];
    const float* bp = (const float*)d_in[5];
    const float* Wr = (const float*)d_in[6];
    const float* br = (const float*)d_in[7];
    float* out = (float*)d_out;

    int8_t *xq1, *xq2, *wq1, *wq2, *pq1, *pq2, *aq1, *aq2;
    float *sx, *sw, *sp, *sa, *af;
    cudaGetSymbolAddress((void**)&xq1, g_xq1); cudaGetSymbolAddress((void**)&xq2, g_xq2);
    cudaGetSymbolAddress((void**)&wq1, g_wq1); cudaGetSymbolAddress((void**)&wq2, g_wq2);
    cudaGetSymbolAddress((void**)&pq1, g_pq1); cudaGetSymbolAddress((void**)&pq2, g_pq2);
    cudaGetSymbolAddress((void**)&aq1, g_aq1); cudaGetSymbolAddress((void**)&aq2, g_aq2);
    cudaGetSymbolAddress((void**)&sx, g_sx);   cudaGetSymbolAddress((void**)&sw, g_sw);
    cudaGetSymbolAddress((void**)&sp, g_sp);   cudaGetSymbolAddress((void**)&sa, g_sa);
    cudaGetSymbolAddress((void**)&af, g_af);

    cudaFuncSetAttribute(gemm_i8<0>, cudaFuncAttributeMaxDynamicSharedMemorySize, IGEMM_SMEM);
    cudaFuncSetAttribute(gemm_i8<3>, cudaFuncAttributeMaxDynamicSharedMemorySize, IGEMM_SMEM);
    cudaFuncSetAttribute(proj_feat, cudaFuncAttributeMaxDynamicSharedMemorySize, PROJ_SMEM);
    cudaFuncSetAttribute(gemm_kv,  cudaFuncAttributeMaxDynamicSharedMemorySize, KV_SMEM);
    cudaFuncSetAttribute(gemm_out, cudaFuncAttributeMaxDynamicSharedMemorySize, OUT_SMEM);

    const int WSZ = DIMV * DIMV;

    quant_rows<<<MROWS / 8, 256>>>(x, xq1, xq2, sx, MROWS);
    quant_rows<<<DIMV / 8, 256>>>(Wq, wq1 + 0 * WSZ, wq2 + 0 * WSZ, sw + 0 * DIMV, DIMV);
    quant_rows<<<DIMV / 8, 256>>>(Wk, wq1 + 1 * WSZ, wq2 + 1 * WSZ, sw + 1 * DIMV, DIMV);
    quant_rows<<<DIMV / 8, 256>>>(Wv, wq1 + 2 * WSZ, wq2 + 2 * WSZ, sw + 2 * DIMV, DIMV);
    quant_rows<<<DIMV / 8, 256>>>(Wp, pq1, pq2, sp, DIMV);
    prep_wrt<<<NHEADS, 256>>>(Wr);
    fill_vt<<<BH * 32, 256>>>();

    // merged QKV int8 GEMM: N = 3072
    gemm_i8<3><<<dim3(3 * DIMV / 128, MROWS / 128), 256, IGEMM_SMEM>>>(
        xq1, xq2, sx, wq1, wq2, sw, nullptr, nullptr);

    proj_feat<<<dim3(MROWS / 128, 32), 256, PROJ_SMEM>>>(br);
    gemm_kv<<<dim3(8, BH * 2), 256, KV_SMEM>>>();
    kv_reduce_t<<<(BH * FEAT * NPAD + 255) / 256, 256>>>();
    gemm_out<<<dim3(SEQ / 128, BH), 256, OUT_SMEM>>>();

    quant_rows<<<MROWS / 8, 256>>>(af, aq1, aq2, sa, MROWS);
    gemm_i8<0><<<dim3(DIMV / 128, MROWS / 128), 256, IGEMM_SMEM>>>(
        aq1, aq2, sa, pq1, pq2, sp, bp, out);
}